// round 1
// baseline (speedup 1.0000x reference)
#include <cuda_runtime.h>

#define BATCH 8
#define HH 480
#define WW 640
#define NPIX (BATCH * HH * WW)
#define TIMES 24

// Scratch (allocation-free rule: __device__ globals)
__device__ float g_weights[BATCH * 9 * HH * WW];   // ~88.5 MB
__device__ float g_buf0[NPIX];                     // ~9.8 MB
__device__ float g_buf1[NPIX];                     // ~9.8 MB

// ---------------------------------------------------------------------------
// Kernel 1: normalize affinity -> 9-tap weights
// affinity: [B, 8, H, W]; weights: [B, 9, H, W], center at tap index 4
// ---------------------------------------------------------------------------
__global__ void __launch_bounds__(128)
weights_kernel(const float* __restrict__ affinity) {
    const int w = blockIdx.x * blockDim.x + threadIdx.x;  // 0..639
    const int h = blockIdx.y;                             // 0..479
    const int b = blockIdx.z;                             // 0..7
    if (w >= WW) return;

    const int plane = HH * WW;
    const int pix   = h * WW + w;
    const float* aff = affinity + (long long)b * 8 * plane + pix;

    float a[8];
    float s = 0.0f;
#pragma unroll
    for (int c = 0; c < 8; c++) {
        a[c] = __ldg(aff + c * plane);
        s += fabsf(a[c]);
    }
    const float inv = 1.0f / s;

    float* wgt = g_weights + (long long)b * 9 * plane + pix;
    float norm_sum = 0.0f;
#pragma unroll
    for (int c = 0; c < 8; c++) {
        a[c] *= inv;
        norm_sum += a[c];
    }
    const float center = 1.0f - norm_sum;

#pragma unroll
    for (int c = 0; c < 4; c++) wgt[c * plane] = a[c];
    wgt[4 * plane] = center;
#pragma unroll
    for (int c = 4; c < 8; c++) wgt[(c + 1) * plane] = a[c];
}

// ---------------------------------------------------------------------------
// Kernel 2: one propagation step.  out[b,h,w] = sum_k wgt[b,k,h,w] * in[b,h+dy,w+dx]
// tap k = i*3+j -> offset (i-1, j-1), zero-padded boundary.
// ---------------------------------------------------------------------------
__global__ void __launch_bounds__(128)
propagate_kernel(const float* __restrict__ fin, float* __restrict__ fout) {
    const int w = blockIdx.x * blockDim.x + threadIdx.x;
    const int h = blockIdx.y;
    const int b = blockIdx.z;
    if (w >= WW) return;

    const int plane = HH * WW;
    const int pix   = h * WW + w;
    const float* wgt = g_weights + (long long)b * 9 * plane + pix;
    const float* src = fin + (long long)b * plane;

    float acc = 0.0f;
#pragma unroll
    for (int k = 0; k < 9; k++) {
        const int dy = k / 3 - 1;
        const int dx = k % 3 - 1;
        const int yy = h + dy;
        const int xx = w + dx;
        float f = 0.0f;
        if (yy >= 0 && yy < HH && xx >= 0 && xx < WW)
            f = __ldg(src + yy * WW + xx);
        acc = fmaf(__ldg(wgt + k * plane), f, acc);
    }
    fout[(long long)b * plane + pix] = acc;
}

// ---------------------------------------------------------------------------
extern "C" void kernel_launch(void* const* d_in, const int* in_sizes, int n_in,
                              void* d_out, int out_size) {
    const float* affinity = (const float*)d_in[0];
    const float* feature  = (const float*)d_in[1];
    float* out = (float*)d_out;

    dim3 blk(128, 1, 1);
    dim3 grd(WW / 128, HH, BATCH);

    weights_kernel<<<grd, blk>>>(affinity);

    // Resolve device-global scratch addresses (host-side symbol addresses are
    // compile-time via cudaGetSymbolAddress is not graph-unsafe, but simpler:
    // launch with the device symbols referenced directly inside a tiny shim).
    // We can take device addresses on host via cudaGetSymbolAddress (not an
    // allocation, graph-capture safe since it's a pure lookup done every call).
    void* p0 = nullptr; void* p1 = nullptr;
    cudaGetSymbolAddress(&p0, g_buf0);
    cudaGetSymbolAddress(&p1, g_buf1);
    float* buf[2] = { (float*)p0, (float*)p1 };

    for (int i = 0; i < TIMES; i++) {
        const float* src = (i == 0) ? feature : buf[i & 1];
        float* dst = (i == TIMES - 1) ? out : buf[(i + 1) & 1];
        propagate_kernel<<<grd, blk>>>(src, dst);
    }
    (void)in_sizes; (void)n_in; (void)out_size;
}

// round 2
// speedup vs baseline: 1.1183x; 1.1183x over previous
#include <cuda_runtime.h>

#define BATCH 8
#define HH 480
#define WW 640
#define PLANE (HH * WW)
#define NPIX (BATCH * PLANE)
#define TIMES 24
#define TFUSE 6                       // iterations fused per launch
#define NLAUNCH (TIMES / TFUSE)       // 4

#define TILE 32                       // output tile
#define CREG (TILE + 2 * (TFUSE - 1)) // 42: compute region
#define RREG (TILE + 2 * TFUSE)       // 44: smem feature region (with halo)
#define BSTR (RREG + 1)               // 45: smem row stride (conflict mitigation)
#define OFF  (TFUSE - 1)              // 5: inner-tile offset inside compute region

// Scratch (allocation-free rule: __device__ globals)
__device__ float g_weights[BATCH * 9 * PLANE];   // ~88.5 MB
__device__ float g_buf0[NPIX];
__device__ float g_buf1[NPIX];

// ---------------------------------------------------------------------------
// Kernel 1: normalize affinity -> 9-tap weights, planar [B,9,H,W], center k=4
// ---------------------------------------------------------------------------
__global__ void __launch_bounds__(128)
weights_kernel(const float* __restrict__ affinity) {
    const int w = blockIdx.x * blockDim.x + threadIdx.x;
    const int h = blockIdx.y;
    const int b = blockIdx.z;
    if (w >= WW) return;

    const int pix = h * WW + w;
    const float* aff = affinity + (long long)b * 8 * PLANE + pix;

    float a[8];
    float s = 0.0f;
#pragma unroll
    for (int c = 0; c < 8; c++) {
        a[c] = __ldg(aff + c * PLANE);
        s += fabsf(a[c]);
    }
    const float inv = 1.0f / s;

    float norm_sum = 0.0f;
#pragma unroll
    for (int c = 0; c < 8; c++) {
        a[c] *= inv;
        norm_sum += a[c];
    }
    const float center = 1.0f - norm_sum;

    float* wgt = g_weights + (long long)b * 9 * PLANE + pix;
#pragma unroll
    for (int c = 0; c < 4; c++) wgt[c * PLANE] = a[c];
    wgt[4 * PLANE] = center;
#pragma unroll
    for (int c = 4; c < 8; c++) wgt[(c + 1) * PLANE] = a[c];
}

// ---------------------------------------------------------------------------
// Kernel 2: TFUSE fused propagation steps on a 32x32 output tile.
//   - feature region 44x44 ping-pongs in smem
//   - per-pixel 9-tap weights live in registers (7 px/thread -> 63 regs),
//     loaded via coalesced plane-by-plane smem staging
//   - compute region fixed at 42x42; staleness creeps 1 ring/iter, so the
//     inner 32x32 is exact after 6 iters
// ---------------------------------------------------------------------------
__global__ void __launch_bounds__(256)
fused_kernel(const float* __restrict__ fin, float* __restrict__ fout) {
    __shared__ float stage[CREG * CREG];          // 42*42 weight staging
    __shared__ float buf[2][RREG * BSTR];         // 2 x 44x45 feature buffers

    const int tid = threadIdx.x;
    const int ox = blockIdx.x * TILE;
    const int oy = blockIdx.y * TILE;
    const int b  = blockIdx.z;

    // ---- load feature region (zero-padded outside the image) ----
    const float* src = fin + (long long)b * PLANE;
#pragma unroll
    for (int i = 0; i < 8; i++) {
        int idx = tid + 256 * i;
        if (idx < RREG * RREG) {
            int by = idx / RREG, bx = idx % RREG;
            int gy = oy - TFUSE + by;
            int gx = ox - TFUSE + bx;
            float v = 0.0f;
            if (gy >= 0 && gy < HH && gx >= 0 && gx < WW)
                v = __ldg(src + gy * WW + gx);
            buf[0][by * BSTR + bx] = v;
        }
    }

    const bool active = (tid < 252);              // 42 rows * 6 groups
    const int row  = tid / 6;                     // compute-region row 0..41
    const int col0 = (tid % 6) * 7;               // first of 7 pixels

    // ---- stage weights plane-by-plane, pick up 7 per thread into regs ----
    float w[7][9];
#pragma unroll
    for (int k = 0; k < 9; k++) {
        __syncthreads();
        const float* wp = g_weights + ((long long)b * 9 + k) * PLANE;
#pragma unroll
        for (int i = 0; i < 7; i++) {
            int idx = tid + 256 * i;
            if (idx < CREG * CREG) {
                int ry = idx / CREG, rx = idx % CREG;
                int gy = oy - OFF + ry;
                int gx = ox - OFF + rx;
                float v = 0.0f;                   // out-of-image pixels: zero
                if (gy >= 0 && gy < HH && gx >= 0 && gx < WW)   // weights so
                    v = __ldg(wp + gy * WW + gx);               // they stay 0
                stage[idx] = v;
            }
        }
        __syncthreads();
        if (active) {
#pragma unroll
            for (int p = 0; p < 7; p++)
                w[p][k] = stage[row * CREG + col0 + p];
        }
    }
    __syncthreads();

    // ---- TFUSE fused iterations ----
    int cur = 0;
#pragma unroll
    for (int t = 0; t < TFUSE; t++) {
        const float* s = buf[cur];
        float* d = buf[cur ^ 1];
        if (active) {
            const int base = row * BSTR + col0;   // buffer row = region row + 1 - 1
            float r0[9], r1[9], r2[9];
#pragma unroll
            for (int j = 0; j < 9; j++) {
                r0[j] = s[base + j];
                r1[j] = s[base + BSTR + j];
                r2[j] = s[base + 2 * BSTR + j];
            }
#pragma unroll
            for (int p = 0; p < 7; p++) {
                float acc;
                acc = w[p][0] * r0[p];
                acc = fmaf(w[p][1], r0[p + 1], acc);
                acc = fmaf(w[p][2], r0[p + 2], acc);
                acc = fmaf(w[p][3], r1[p],     acc);
                acc = fmaf(w[p][4], r1[p + 1], acc);
                acc = fmaf(w[p][5], r1[p + 2], acc);
                acc = fmaf(w[p][6], r2[p],     acc);
                acc = fmaf(w[p][7], r2[p + 1], acc);
                acc = fmaf(w[p][8], r2[p + 2], acc);
                d[(row + 1) * BSTR + col0 + 1 + p] = acc;
            }
        }
        __syncthreads();
        cur ^= 1;
    }

    // ---- write inner 32x32 (result in buf[0]: TFUSE is even) ----
    if (active && row >= OFF && row < OFF + TILE) {
        float* out = fout + (long long)b * PLANE;
        const int gy = oy + row - OFF;
#pragma unroll
        for (int p = 0; p < 7; p++) {
            int col = col0 + p;
            if (col >= OFF && col < OFF + TILE)
                out[gy * WW + ox + col - OFF] = buf[0][(row + 1) * BSTR + col + 1];
        }
    }
}

// ---------------------------------------------------------------------------
extern "C" void kernel_launch(void* const* d_in, const int* in_sizes, int n_in,
                              void* d_out, int out_size) {
    const float* affinity = (const float*)d_in[0];
    const float* feature  = (const float*)d_in[1];
    float* out = (float*)d_out;

    dim3 wblk(128, 1, 1);
    dim3 wgrd(WW / 128, HH, BATCH);
    weights_kernel<<<wgrd, wblk>>>(affinity);

    void* p0 = nullptr; void* p1 = nullptr;
    cudaGetSymbolAddress(&p0, g_buf0);
    cudaGetSymbolAddress(&p1, g_buf1);
    float* buf[2] = { (float*)p0, (float*)p1 };

    dim3 fblk(256, 1, 1);
    dim3 fgrd(WW / TILE, HH / TILE, BATCH);   // 20 x 15 x 8

    // feature -> buf0 -> buf1 -> buf0 -> out   (4 launches x 6 fused iters)
    const float* cursrc = feature;
    for (int l = 0; l < NLAUNCH; l++) {
        float* dst = (l == NLAUNCH - 1) ? out : buf[l & 1];
        fused_kernel<<<fgrd, fblk>>>(cursrc, dst);
        cursrc = dst;
    }
    (void)in_sizes; (void)n_in; (void)out_size;
}

// round 3
// speedup vs baseline: 1.5262x; 1.3647x over previous
#include <cuda_runtime.h>

#define BATCH 8
#define HH 480
#define WW 640
#define PLANE (HH * WW)
#define NPIX (BATCH * PLANE)
#define TIMES 24
#define TFUSE 6
#define NLAUNCH (TIMES / TFUSE)   // 4

#define TILE 32
#define OFF  (TFUSE - 1)          // 5
#define CROWS (TILE + 2 * OFF)    // 42 compute rows (cols padded to 44)
#define NGRP 11                   // 11 groups of 4 cols -> cols 0..43 (42,43 junk)
#define NACT (CROWS * NGRP)       // 462 active threads
#define BROWS (TILE + 2 * TFUSE)  // 44 buffer rows (region row -1..42)
#define BW 48                     // buffer width (cols 0..43 real, 44..47 zero)
#define NTHREADS 512

// Scratch (allocation-free rule: __device__ globals)
__device__ float g_weights[(size_t)BATCH * 9 * PLANE];  // ~88.5 MB
__device__ float g_buf0[NPIX];
__device__ float g_buf1[NPIX];

// ---------------------------------------------------------------------------
// Kernel 1: normalize affinity -> 9-tap weights, planar [B,9,H,W], float4-wide
// ---------------------------------------------------------------------------
__global__ void __launch_bounds__(256)
weights_kernel(const float* __restrict__ affinity) {
    const int i4 = blockIdx.x * blockDim.x + threadIdx.x;  // pixel/4
    const int b  = blockIdx.y;
    if (i4 >= PLANE / 4) return;

    const float4* aff = (const float4*)(affinity + (size_t)b * 8 * PLANE) + i4;
    float4 a[8];
    float4 s = make_float4(0.f, 0.f, 0.f, 0.f);
#pragma unroll
    for (int c = 0; c < 8; c++) {
        a[c] = __ldg(aff + (size_t)c * (PLANE / 4));
        s.x += fabsf(a[c].x); s.y += fabsf(a[c].y);
        s.z += fabsf(a[c].z); s.w += fabsf(a[c].w);
    }
    const float4 inv = make_float4(1.f / s.x, 1.f / s.y, 1.f / s.z, 1.f / s.w);
    float4 ns = make_float4(0.f, 0.f, 0.f, 0.f);
#pragma unroll
    for (int c = 0; c < 8; c++) {
        a[c].x *= inv.x; a[c].y *= inv.y; a[c].z *= inv.z; a[c].w *= inv.w;
        ns.x += a[c].x; ns.y += a[c].y; ns.z += a[c].z; ns.w += a[c].w;
    }
    const float4 center = make_float4(1.f - ns.x, 1.f - ns.y, 1.f - ns.z, 1.f - ns.w);

    float4* wgt = (float4*)(g_weights + (size_t)b * 9 * PLANE) + i4;
#pragma unroll
    for (int c = 0; c < 4; c++) wgt[(size_t)c * (PLANE / 4)] = a[c];
    wgt[(size_t)4 * (PLANE / 4)] = center;
#pragma unroll
    for (int c = 4; c < 8; c++) wgt[(size_t)(c + 1) * (PLANE / 4)] = a[c];
}

// ---------------------------------------------------------------------------
// Kernel 2: TFUSE fused steps; 4 px/thread, weights in 36 regs, vector LDS.
// ---------------------------------------------------------------------------
__global__ void __launch_bounds__(NTHREADS, 2)
fused_kernel(const float* __restrict__ fin, float* __restrict__ fout) {
    __shared__ __align__(16) float buf[2][BROWS * BW];

    const int tid = threadIdx.x;
    const int ox = blockIdx.x * TILE;
    const int oy = blockIdx.y * TILE;
    const int b  = blockIdx.z;

    // ---- load feature region into buf0 (zero-pad), zero buf1 ----
    const float* src = fin + (size_t)b * PLANE;
#pragma unroll
    for (int idx = tid; idx < BROWS * BW; idx += NTHREADS) {
        const int br = idx / BW, bc = idx % BW;
        const int gy = oy - TFUSE + br;
        const int gx = ox - TFUSE + bc;
        float v = 0.f;
        if (bc < BROWS && gy >= 0 && gy < HH && gx >= 0 && gx < WW)
            v = __ldg(src + gy * WW + gx);
        buf[0][idx] = v;
        buf[1][idx] = 0.f;
    }

    // ---- per-thread weights straight from gmem (36 independent LDGs) ----
    const bool active = (tid < NACT);
    const int row  = tid / NGRP;        // region row 0..41
    const int col0 = (tid % NGRP) * 4;  // region cols col0..col0+3
    float w[9][4];
    if (active) {
        const int gy = oy - OFF + row;
        const float* wb = g_weights + (size_t)b * 9 * PLANE;
        const bool yok = (gy >= 0 && gy < HH);
#pragma unroll
        for (int k = 0; k < 9; k++) {
#pragma unroll
            for (int p = 0; p < 4; p++) {
                const int gx = ox - OFF + col0 + p;
                float v = 0.f;
                if (yok && gx >= 0 && gx < WW)
                    v = __ldg(wb + (size_t)k * PLANE + gy * WW + gx);
                w[k][p] = v;
            }
        }
    }
    __syncthreads();

    // ---- TFUSE fused iterations ----
    int cur = 0;
#pragma unroll
    for (int t = 0; t < TFUSE; t++) {
        const float* s = buf[cur];
        float* d = buf[cur ^ 1];
        if (active) {
            float a0 = 0.f, a1 = 0.f, a2 = 0.f, a3 = 0.f;
#pragma unroll
            for (int rr = 0; rr < 3; rr++) {
                const float* sp = s + (row + rr) * BW + col0;
                const float4 v4 = *(const float4*)sp;
                const float2 v2 = *(const float2*)(sp + 4);
                a0 = fmaf(w[3*rr+0][0], v4.x, fmaf(w[3*rr+1][0], v4.y, fmaf(w[3*rr+2][0], v4.z, a0)));
                a1 = fmaf(w[3*rr+0][1], v4.y, fmaf(w[3*rr+1][1], v4.z, fmaf(w[3*rr+2][1], v4.w, a1)));
                a2 = fmaf(w[3*rr+0][2], v4.z, fmaf(w[3*rr+1][2], v4.w, fmaf(w[3*rr+2][2], v2.x, a2)));
                a3 = fmaf(w[3*rr+0][3], v4.w, fmaf(w[3*rr+1][3], v2.x, fmaf(w[3*rr+2][3], v2.y, a3)));
            }
            float* dp = d + (row + 1) * BW + col0 + 1;
            dp[0] = a0; dp[1] = a1; dp[2] = a2; dp[3] = a3;
        }
        __syncthreads();
        cur ^= 1;
    }

    // ---- write inner 32x32 (result in buf[0]: TFUSE even) ----
    float* out = fout + (size_t)b * PLANE;
    const float* r = buf[0];
#pragma unroll
    for (int idx = tid; idx < TILE * TILE; idx += NTHREADS) {
        const int rr = idx / TILE, cc = idx % TILE;
        out[(oy + rr) * WW + ox + cc] = r[(rr + OFF + 1) * BW + cc + OFF + 1];
    }
}

// ---------------------------------------------------------------------------
extern "C" void kernel_launch(void* const* d_in, const int* in_sizes, int n_in,
                              void* d_out, int out_size) {
    const float* affinity = (const float*)d_in[0];
    const float* feature  = (const float*)d_in[1];
    float* out = (float*)d_out;

    dim3 wblk(256, 1, 1);
    dim3 wgrd((PLANE / 4 + 255) / 256, BATCH, 1);   // 300 x 8
    weights_kernel<<<wgrd, wblk>>>(affinity);

    void* p0 = nullptr; void* p1 = nullptr;
    cudaGetSymbolAddress(&p0, g_buf0);
    cudaGetSymbolAddress(&p1, g_buf1);
    float* buf[2] = { (float*)p0, (float*)p1 };

    dim3 fblk(NTHREADS, 1, 1);
    dim3 fgrd(WW / TILE, HH / TILE, BATCH);         // 20 x 15 x 8

    const float* cursrc = feature;
    for (int l = 0; l < NLAUNCH; l++) {
        float* dst = (l == NLAUNCH - 1) ? out : buf[l & 1];
        fused_kernel<<<fgrd, fblk>>>(cursrc, dst);
        cursrc = dst;
    }
    (void)in_sizes; (void)n_in; (void)out_size;
}

// round 4
// speedup vs baseline: 1.8031x; 1.1815x over previous
#include <cuda_runtime.h>

#define BATCH 8
#define HH 480
#define WW 640
#define PLANE (HH * WW)
#define NPIX (BATCH * PLANE)
#define TIMES 24
#define TFUSE 6
#define NLAUNCH (TIMES / TFUSE)   // 4

#define TILE 32
#define OFF  (TFUSE - 1)          // 5 : inner tile at region rows 5..36
#define CROWS 42                  // compute rows: gy = oy-5 .. oy+36
#define NGRP 12                   // 12 groups of 4 cols: gx = ox-8 .. ox+39
#define NACT (CROWS * NGRP)       // 504 active threads
#define BROWS 44                  // buffer rows: region rows -1..42
#define BSTR 56                   // buffer cols: gx = ox-12 .. ox+43 (region col rc -> buf col rc+4)
#define NTHREADS 512

// Scratch (allocation-free rule: __device__ globals)
__device__ float g_weights[(size_t)BATCH * 9 * PLANE];  // ~88.5 MB
__device__ float g_buf0[NPIX];
__device__ float g_buf1[NPIX];

// ---------------------------------------------------------------------------
// Kernel 1: normalize affinity -> 9-tap weights, planar [B,9,H,W], float4
// ---------------------------------------------------------------------------
__global__ void __launch_bounds__(256)
weights_kernel(const float* __restrict__ affinity) {
    const int i4 = blockIdx.x * blockDim.x + threadIdx.x;
    const int b  = blockIdx.y;
    if (i4 >= PLANE / 4) return;

    const float4* aff = (const float4*)(affinity + (size_t)b * 8 * PLANE) + i4;
    float4 a[8];
    float4 s = make_float4(0.f, 0.f, 0.f, 0.f);
#pragma unroll
    for (int c = 0; c < 8; c++) {
        a[c] = __ldg(aff + (size_t)c * (PLANE / 4));
        s.x += fabsf(a[c].x); s.y += fabsf(a[c].y);
        s.z += fabsf(a[c].z); s.w += fabsf(a[c].w);
    }
    const float4 inv = make_float4(1.f / s.x, 1.f / s.y, 1.f / s.z, 1.f / s.w);
    float4 ns = make_float4(0.f, 0.f, 0.f, 0.f);
#pragma unroll
    for (int c = 0; c < 8; c++) {
        a[c].x *= inv.x; a[c].y *= inv.y; a[c].z *= inv.z; a[c].w *= inv.w;
        ns.x += a[c].x; ns.y += a[c].y; ns.z += a[c].z; ns.w += a[c].w;
    }
    const float4 center = make_float4(1.f - ns.x, 1.f - ns.y, 1.f - ns.z, 1.f - ns.w);

    float4* wgt = (float4*)(g_weights + (size_t)b * 9 * PLANE) + i4;
#pragma unroll
    for (int c = 0; c < 4; c++) wgt[(size_t)c * (PLANE / 4)] = a[c];
    wgt[(size_t)4 * (PLANE / 4)] = center;
#pragma unroll
    for (int c = 4; c < 8; c++) wgt[(size_t)(c + 1) * (PLANE / 4)] = a[c];
}

// ---------------------------------------------------------------------------
// Kernel 2: TFUSE fused steps; 4 px/thread; vectorized weight LDG.128,
// aligned STS.128/LDS, final iteration writes gmem straight from registers.
// ---------------------------------------------------------------------------
__global__ void __launch_bounds__(NTHREADS, 2)
fused_kernel(const float* __restrict__ fin, float* __restrict__ fout) {
    __shared__ __align__(16) float buf[2][BROWS * BSTR];

    const int tid = threadIdx.x;
    const int ox = blockIdx.x * TILE;
    const int oy = blockIdx.y * TILE;
    const int b  = blockIdx.z;

    // ---- load feature window (region + 1 ring) into BOTH buffers ----
    const float* src = fin + (size_t)b * PLANE;
#pragma unroll
    for (int idx = tid; idx < BROWS * BSTR; idx += NTHREADS) {
        const int br = idx / BSTR, bc = idx % BSTR;
        const int gy = oy - 6  + br;      // buffer row br <-> region row br-1
        const int gx = ox - 12 + bc;      // buffer col bc <-> region col bc-4
        float v = 0.f;
        if (gy >= 0 && gy < HH && gx >= 0 && gx < WW)
            v = __ldg(src + gy * WW + gx);
        buf[0][idx] = v;
        buf[1][idx] = v;                  // fresh ring in both ping-pong bufs
    }

    // ---- per-thread weights: 9 x LDG.128 (fully in- or out-of-image) ----
    const bool active = (tid < NACT);
    const int row  = tid / NGRP;          // region row 0..41
    const int grp  = tid % NGRP;
    const int col0 = grp * 4;             // region cols col0..col0+3
    const int gy   = oy - OFF + row;
    const int gx0  = ox - 8 + col0;       // 4-aligned global col

    float4 w4[9];
    {
        const bool ok = active && gy >= 0 && gy < HH && gx0 >= 0 && gx0 < WW;
        const float4 z = make_float4(0.f, 0.f, 0.f, 0.f);
        const float* wb = g_weights + (size_t)b * 9 * PLANE + gy * WW + gx0;
#pragma unroll
        for (int k = 0; k < 9; k++)
            w4[k] = ok ? __ldg((const float4*)(wb + (size_t)k * PLANE)) : z;
    }
    __syncthreads();

    // ---- TFUSE fused iterations ----
    const int bcol = col0 + 4;            // aligned buffer col of output group
    float a0, a1, a2, a3;
    int cur = 0;
#pragma unroll
    for (int t = 0; t < TFUSE; t++) {
        const float* s = buf[cur];
        if (active) {
            a0 = a1 = a2 = a3 = 0.f;
#pragma unroll
            for (int rr = 0; rr < 3; rr++) {
                // taps at buffer cols bcol-1 .. bcol+4 on buffer row (row+rr)
                const float* sp = s + (row + rr) * BSTR + bcol;
                const float2 lv = *(const float2*)(sp - 2);   // .y = bcol-1
                const float4 cv = *(const float4*)(sp);        // bcol..bcol+3
                const float2 rv = *(const float2*)(sp + 4);    // .x = bcol+4
                const float f0 = lv.y, f1 = cv.x, f2 = cv.y,
                            f3 = cv.z, f4 = cv.w, f5 = rv.x;
                const float4 wa = w4[3 * rr + 0];
                const float4 wbm = w4[3 * rr + 1];
                const float4 wc = w4[3 * rr + 2];
                a0 = fmaf(wa.x, f0, fmaf(wbm.x, f1, fmaf(wc.x, f2, a0)));
                a1 = fmaf(wa.y, f1, fmaf(wbm.y, f2, fmaf(wc.y, f3, a1)));
                a2 = fmaf(wa.z, f2, fmaf(wbm.z, f3, fmaf(wc.z, f4, a2)));
                a3 = fmaf(wa.w, f3, fmaf(wbm.w, f4, fmaf(wc.w, f5, a3)));
            }
            if (t < TFUSE - 1) {
                float* dp = buf[cur ^ 1] + (row + 1) * BSTR + bcol;
                *(float4*)dp = make_float4(a0, a1, a2, a3);    // aligned STS.128
            }
        }
        if (t < TFUSE - 1) __syncthreads();
        cur ^= 1;
    }

    // ---- final: inner 32x32 straight from registers (aligned STG.128) ----
    if (active && row >= OFF && row < OFF + TILE && grp >= 2 && grp < 10) {
        float* out = fout + (size_t)b * PLANE;
        *(float4*)(out + gy * WW + gx0) = make_float4(a0, a1, a2, a3);
    }
}

// ---------------------------------------------------------------------------
extern "C" void kernel_launch(void* const* d_in, const int* in_sizes, int n_in,
                              void* d_out, int out_size) {
    const float* affinity = (const float*)d_in[0];
    const float* feature  = (const float*)d_in[1];
    float* out = (float*)d_out;

    dim3 wblk(256, 1, 1);
    dim3 wgrd((PLANE / 4 + 255) / 256, BATCH, 1);
    weights_kernel<<<wgrd, wblk>>>(affinity);

    void* p0 = nullptr; void* p1 = nullptr;
    cudaGetSymbolAddress(&p0, g_buf0);
    cudaGetSymbolAddress(&p1, g_buf1);
    float* buf[2] = { (float*)p0, (float*)p1 };

    dim3 fblk(NTHREADS, 1, 1);
    dim3 fgrd(WW / TILE, HH / TILE, BATCH);   // 20 x 15 x 8

    const float* cursrc = feature;
    for (int l = 0; l < NLAUNCH; l++) {
        float* dst = (l == NLAUNCH - 1) ? out : buf[l & 1];
        fused_kernel<<<fgrd, fblk>>>(cursrc, dst);
        cursrc = dst;
    }
    (void)in_sizes; (void)n_in; (void)out_size;
}

// round 5
// speedup vs baseline: 2.0988x; 1.1640x over previous
#include <cuda_runtime.h>

#define BATCH 8
#define HH 480
#define WW 640
#define PLANE (HH * WW)
#define NPIX (BATCH * PLANE)
#define TIMES 24
#define TFUSE 6
#define NLAUNCH (TIMES / TFUSE)   // 4

#define TILE_X 64
#define TILE_Y 32
#define OFF  (TFUSE - 1)          // 5
#define CROWS 42                  // computed rows: gy = oy-5 .. oy+36
#define NGRP 20                   // 20 groups of 4: gx = ox-8 .. ox+71
#define NACT (CROWS * NGRP)       // 840 active threads
#define BROWS 44                  // buffer rows: gy = oy-6 .. oy+37
#define BSTR 92                   // buffer cols: gx = ox-12 .. ox+79 (23 float4s: odd)
#define NTHREADS 864

// Scratch (allocation-free rule: __device__ globals)
__device__ float g_buf0[NPIX];
__device__ float g_buf1[NPIX];

// ---------------------------------------------------------------------------
// Fused kernel: loads 8 affinity planes per thread-pixel-group, normalizes to
// 9 tap weights in registers, then runs TFUSE propagation steps in smem.
// ---------------------------------------------------------------------------
__global__ void __launch_bounds__(NTHREADS, 1)
fused_kernel(const float* __restrict__ affinity,
             const float* __restrict__ fin, float* __restrict__ fout) {
    __shared__ __align__(16) float buf[2][BROWS * BSTR];

    const int tid = threadIdx.x;
    const int ox = blockIdx.x * TILE_X;
    const int oy = blockIdx.y * TILE_Y;
    const int b  = blockIdx.z;

    // ---- load feature window (computed region + static ring) into BOTH bufs
    const float* src = fin + (size_t)b * PLANE;
#pragma unroll
    for (int idx = tid; idx < BROWS * BSTR; idx += NTHREADS) {
        const int br = idx / BSTR, bc = idx % BSTR;
        const int gy = oy - 6  + br;
        const int gx = ox - 12 + bc;
        float v = 0.f;
        if (gy >= 0 && gy < HH && gx >= 0 && gx < WW)
            v = __ldg(src + gy * WW + gx);
        buf[0][idx] = v;
        buf[1][idx] = v;
    }

    // ---- per-thread: load 8 affinity float4s, normalize -> 9 tap weights ---
    const bool active = (tid < NACT);
    const int row  = tid / NGRP;          // region row 0..41
    const int grp  = tid % NGRP;
    const int col0 = grp * 4;
    const int gy   = oy - OFF + row;
    const int gx0  = ox - 8 + col0;       // 4-aligned

    float4 w4[9];
    {
        const bool ok = active && gy >= 0 && gy < HH && gx0 >= 0 && gx0 < WW;
        const float4 z = make_float4(0.f, 0.f, 0.f, 0.f);
        if (ok) {
            const float* ab = affinity + (size_t)b * 8 * PLANE + gy * WW + gx0;
            float4 a[8];
            float4 s = z;
#pragma unroll
            for (int c = 0; c < 8; c++) {
                a[c] = __ldg((const float4*)(ab + (size_t)c * PLANE));
                s.x += fabsf(a[c].x); s.y += fabsf(a[c].y);
                s.z += fabsf(a[c].z); s.w += fabsf(a[c].w);
            }
            const float4 inv = make_float4(1.f/s.x, 1.f/s.y, 1.f/s.z, 1.f/s.w);
            float4 ns = z;
#pragma unroll
            for (int c = 0; c < 8; c++) {
                a[c].x *= inv.x; a[c].y *= inv.y;
                a[c].z *= inv.z; a[c].w *= inv.w;
                ns.x += a[c].x; ns.y += a[c].y;
                ns.z += a[c].z; ns.w += a[c].w;
            }
#pragma unroll
            for (int c = 0; c < 4; c++) w4[c] = a[c];
            w4[4] = make_float4(1.f - ns.x, 1.f - ns.y, 1.f - ns.z, 1.f - ns.w);
#pragma unroll
            for (int c = 4; c < 8; c++) w4[c + 1] = a[c];
        } else {
#pragma unroll
            for (int k = 0; k < 9; k++) w4[k] = z;
        }
    }
    __syncthreads();

    // ---- TFUSE fused iterations ----
    const int bcol = col0 + 4;            // aligned buffer col of output group
    float a0, a1, a2, a3;
    int cur = 0;
#pragma unroll
    for (int t = 0; t < TFUSE; t++) {
        const float* s = buf[cur];
        if (active) {
            a0 = a1 = a2 = a3 = 0.f;
#pragma unroll
            for (int rr = 0; rr < 3; rr++) {
                const float* sp = s + (row + rr) * BSTR + bcol;
                const float2 lv = *(const float2*)(sp - 2);   // .y = bcol-1
                const float4 cv = *(const float4*)(sp);
                const float2 rv = *(const float2*)(sp + 4);   // .x = bcol+4
                const float f0 = lv.y, f1 = cv.x, f2 = cv.y,
                            f3 = cv.z, f4 = cv.w, f5 = rv.x;
                const float4 wa = w4[3 * rr + 0];
                const float4 wb = w4[3 * rr + 1];
                const float4 wc = w4[3 * rr + 2];
                a0 = fmaf(wa.x, f0, fmaf(wb.x, f1, fmaf(wc.x, f2, a0)));
                a1 = fmaf(wa.y, f1, fmaf(wb.y, f2, fmaf(wc.y, f3, a1)));
                a2 = fmaf(wa.z, f2, fmaf(wb.z, f3, fmaf(wc.z, f4, a2)));
                a3 = fmaf(wa.w, f3, fmaf(wb.w, f4, fmaf(wc.w, f5, a3)));
            }
            if (t < TFUSE - 1) {
                float* dp = buf[cur ^ 1] + (row + 1) * BSTR + bcol;
                *(float4*)dp = make_float4(a0, a1, a2, a3);    // STS.128
            }
        }
        if (t < TFUSE - 1) __syncthreads();
        cur ^= 1;
    }

    // ---- final: inner 64x32 straight from registers (STG.128) ----
    if (active && row >= OFF && row < OFF + TILE_Y && grp >= 2 && grp < 18) {
        float* out = fout + (size_t)b * PLANE;
        *(float4*)(out + gy * WW + gx0) = make_float4(a0, a1, a2, a3);
    }
}

// ---------------------------------------------------------------------------
extern "C" void kernel_launch(void* const* d_in, const int* in_sizes, int n_in,
                              void* d_out, int out_size) {
    const float* affinity = (const float*)d_in[0];
    const float* feature  = (const float*)d_in[1];
    float* out = (float*)d_out;

    void* p0 = nullptr; void* p1 = nullptr;
    cudaGetSymbolAddress(&p0, g_buf0);
    cudaGetSymbolAddress(&p1, g_buf1);
    float* buf[2] = { (float*)p0, (float*)p1 };

    dim3 fblk(NTHREADS, 1, 1);
    dim3 fgrd(WW / TILE_X, HH / TILE_Y, BATCH);   // 10 x 15 x 8

    const float* cursrc = feature;
    for (int l = 0; l < NLAUNCH; l++) {
        float* dst = (l == NLAUNCH - 1) ? out : buf[l & 1];
        fused_kernel<<<fgrd, fblk>>>(affinity, cursrc, dst);
        cursrc = dst;
    }
    (void)in_sizes; (void)n_in; (void)out_size;
}

// round 6
// speedup vs baseline: 2.1753x; 1.0365x over previous
#include <cuda_runtime.h>

#define BATCH 8
#define HH 480
#define WW 640
#define PLANE (HH * WW)
#define NPIX (BATCH * PLANE)
#define TIMES 24
#define TFUSE 8
#define NLAUNCH (TIMES / TFUSE)   // 3

#define TILE_X 64
#define TILE_Y 32
#define OFF  (TFUSE - 1)          // 7 : inner tile at region rows 7..38
#define CROWS 46                  // computed rows: gy = oy-7 .. oy+38
#define NGRP 20                   // 20 groups of 4: gx = ox-8 .. ox+71
#define NACT (CROWS * NGRP)       // 920 active threads
#define BROWS 48                  // buffer rows: region rows -1..46
#define BSTR 92                   // buffer cols: gx = ox-12 .. ox+79
#define NTHREADS 1024

// Scratch (allocation-free rule: __device__ globals)
__device__ float g_buf0[NPIX];
__device__ float g_buf1[NPIX];

// ---------------------------------------------------------------------------
// Fused kernel: per-thread affinity load + normalize -> 9 tap weights in regs,
// then TFUSE propagation steps ping-ponging a 48x92 window in smem.
// ---------------------------------------------------------------------------
__global__ void __launch_bounds__(NTHREADS, 1)
fused_kernel(const float* __restrict__ affinity,
             const float* __restrict__ fin, float* __restrict__ fout) {
    __shared__ __align__(16) float buf[2][BROWS * BSTR];

    const int tid = threadIdx.x;
    const int ox = blockIdx.x * TILE_X;
    const int oy = blockIdx.y * TILE_Y;
    const int b  = blockIdx.z;

    // ---- load feature window; full into buf0, ring-only into buf1 ----
    const float* src = fin + (size_t)b * PLANE;
#pragma unroll
    for (int idx = tid; idx < BROWS * BSTR; idx += NTHREADS) {
        const int br = idx / BSTR, bc = idx % BSTR;
        const int gy = oy - 8  + br;      // buffer row br <-> region row br-1
        const int gx = ox - 12 + bc;      // buffer col bc <-> region col bc-4
        float v = 0.f;
        if (gy >= 0 && gy < HH && gx >= 0 && gx < WW)
            v = __ldg(src + gy * WW + gx);
        buf[0][idx] = v;
        if (br == 0 || br == BROWS - 1 || bc < 4 || bc > 83)
            buf[1][idx] = v;              // static ring (never recomputed)
    }

    // ---- per-thread: 8 affinity float4 LDGs, normalize -> 9 tap weights ----
    const bool active = (tid < NACT);
    const int row  = tid / NGRP;          // region row 0..45
    const int grp  = tid % NGRP;
    const int col0 = grp * 4;
    const int gy   = oy - OFF + row;
    const int gx0  = ox - 8 + col0;       // 4-aligned

    float4 w4[9];
    {
        const bool ok = active && gy >= 0 && gy < HH && gx0 >= 0 && gx0 < WW;
        const float4 z = make_float4(0.f, 0.f, 0.f, 0.f);
        if (ok) {
            const float* ab = affinity + (size_t)b * 8 * PLANE + gy * WW + gx0;
            float4 a[8];
            float4 s = z;
#pragma unroll
            for (int c = 0; c < 8; c++) {
                a[c] = __ldg((const float4*)(ab + (size_t)c * PLANE));
                s.x += fabsf(a[c].x); s.y += fabsf(a[c].y);
                s.z += fabsf(a[c].z); s.w += fabsf(a[c].w);
            }
            const float4 inv = make_float4(1.f/s.x, 1.f/s.y, 1.f/s.z, 1.f/s.w);
            float4 ns = z;
#pragma unroll
            for (int c = 0; c < 8; c++) {
                a[c].x *= inv.x; a[c].y *= inv.y;
                a[c].z *= inv.z; a[c].w *= inv.w;
                ns.x += a[c].x; ns.y += a[c].y;
                ns.z += a[c].z; ns.w += a[c].w;
            }
#pragma unroll
            for (int c = 0; c < 4; c++) w4[c] = a[c];
            w4[4] = make_float4(1.f - ns.x, 1.f - ns.y, 1.f - ns.z, 1.f - ns.w);
#pragma unroll
            for (int c = 4; c < 8; c++) w4[c + 1] = a[c];
        } else {
#pragma unroll
            for (int k = 0; k < 9; k++) w4[k] = z;
        }
    }
    __syncthreads();

    // ---- TFUSE fused iterations ----
    const int bcol = col0 + 4;            // aligned buffer col of output group
    float a0, a1, a2, a3;
    int cur = 0;
#pragma unroll
    for (int t = 0; t < TFUSE; t++) {
        const float* s = buf[cur];
        if (active) {
            a0 = a1 = a2 = a3 = 0.f;
#pragma unroll
            for (int rr = 0; rr < 3; rr++) {
                const float* sp = s + (row + rr) * BSTR + bcol;
                const float2 lv = *(const float2*)(sp - 2);   // .y = bcol-1
                const float4 cv = *(const float4*)(sp);
                const float2 rv = *(const float2*)(sp + 4);   // .x = bcol+4
                const float f0 = lv.y, f1 = cv.x, f2 = cv.y,
                            f3 = cv.z, f4 = cv.w, f5 = rv.x;
                const float4 wa = w4[3 * rr + 0];
                const float4 wb = w4[3 * rr + 1];
                const float4 wc = w4[3 * rr + 2];
                a0 = fmaf(wa.x, f0, fmaf(wb.x, f1, fmaf(wc.x, f2, a0)));
                a1 = fmaf(wa.y, f1, fmaf(wb.y, f2, fmaf(wc.y, f3, a1)));
                a2 = fmaf(wa.z, f2, fmaf(wb.z, f3, fmaf(wc.z, f4, a2)));
                a3 = fmaf(wa.w, f3, fmaf(wb.w, f4, fmaf(wc.w, f5, a3)));
            }
            if (t < TFUSE - 1) {
                float* dp = buf[cur ^ 1] + (row + 1) * BSTR + bcol;
                *(float4*)dp = make_float4(a0, a1, a2, a3);    // STS.128
            }
        }
        if (t < TFUSE - 1) __syncthreads();
        cur ^= 1;
    }

    // ---- final: inner 64x32 straight from registers (STG.128) ----
    if (active && row >= OFF && row < OFF + TILE_Y && grp >= 2 && grp < 18) {
        float* out = fout + (size_t)b * PLANE;
        *(float4*)(out + gy * WW + gx0) = make_float4(a0, a1, a2, a3);
    }
}

// ---------------------------------------------------------------------------
extern "C" void kernel_launch(void* const* d_in, const int* in_sizes, int n_in,
                              void* d_out, int out_size) {
    const float* affinity = (const float*)d_in[0];
    const float* feature  = (const float*)d_in[1];
    float* out = (float*)d_out;

    void* p0 = nullptr; void* p1 = nullptr;
    cudaGetSymbolAddress(&p0, g_buf0);
    cudaGetSymbolAddress(&p1, g_buf1);
    float* buf[2] = { (float*)p0, (float*)p1 };

    dim3 fblk(NTHREADS, 1, 1);
    dim3 fgrd(WW / TILE_X, HH / TILE_Y, BATCH);   // 10 x 15 x 8

    const float* cursrc = feature;
    for (int l = 0; l < NLAUNCH; l++) {
        float* dst = (l == NLAUNCH - 1) ? out : buf[l & 1];
        fused_kernel<<<fgrd, fblk>>>(affinity, cursrc, dst);
        cursrc = dst;
    }
    (void)in_sizes; (void)n_in; (void)out_size;
}